// round 5
// baseline (speedup 1.0000x reference)
#include <cuda_runtime.h>
#include <cuda_bf16.h>
#include <mma.h>
#include <cstdint>

using namespace nvcuda;

// NARX: B=256, T=2048, d_x=32, d_y=32, d_hl=512, D_I=8, D_O=4
#define BATCH 256
#define TSEQ  2048
#define DX    32
#define DY    32
#define DH    512
#define DI    8
#define DO    4
#define STEPS (TSEQ - DI)   /* 2040 */
#define DIN   384

// fp32 scratch: Hx[b][t][j] = x-window part of layer1 pre-activation + b1
__device__ float g_hx[(size_t)BATCH * STEPS * DH];

// ===========================================================================
// Phase A: Hx GEMM via wmma tf32. Block tile M=256 (t rows), N=128 (j), K=256.
// A[t][k] = x_flat[b][32*t + k]  (overlapped windows -> smem slice, ld = 32)
// B[k][j] = W1[j][k]             (stored [j][k] w/ stride 264, col_major load)
// 256 threads = 8 warps as 4(m) x 2(n); warp tile 64x64 = 4x4 m16n16 frags.
// ===========================================================================

#define XS_N   8416            // max logical idx 255*32+255 = 8415
#define WS_LD  264             // 256 + 8 pad
#define CB_LD  132

__global__ void __launch_bounds__(256, 1)
narx_hx(const float* __restrict__ x, const float* __restrict__ W1,
        const float* __restrict__ b1)
{
    extern __shared__ float sm[];
    float* xs = sm;                    // 8416 floats
    float* ws = sm + XS_N;             // 128*264 = 33792 floats

    const int tid  = threadIdx.x;
    const int warp = tid >> 5;
    const int wm   = warp & 3;
    const int wn   = warp >> 2;
    const int t0   = blockIdx.x * 256;
    const int J0   = blockIdx.y * 128;
    const int b    = blockIdx.z;

    // stage x slice, tf32-rounded
    {
        const float* xb = x + (size_t)b * (TSEQ * DX) + (size_t)t0 * DX;
        const int lim = TSEQ * DX - t0 * DX;
        for (int i = tid; i < XS_N; i += 256) {
            float v = (i < lim) ? xb[i] : 0.0f;
            xs[i] = wmma::__float_to_tf32(v);
        }
    }
    // stage W1 x-part tile [128 j][256 k], tf32-rounded
    for (int idx = tid; idx < 128 * 256; idx += 256) {
        int jj = idx >> 8, k = idx & 255;
        ws[jj * WS_LD + k] = wmma::__float_to_tf32(W1[(size_t)(J0 + jj) * DIN + k]);
    }
    __syncthreads();

    wmma::fragment<wmma::accumulator, 16, 16, 8, float> c[4][4];
    #pragma unroll
    for (int i = 0; i < 4; i++)
        #pragma unroll
        for (int j = 0; j < 4; j++) wmma::fill_fragment(c[i][j], 0.0f);

    const float* abase = xs + (wm * 64) * 32;
    const float* bbase = ws + (wn * 64) * WS_LD;

    #pragma unroll 1
    for (int kk = 0; kk < 32; ++kk) {
        wmma::fragment<wmma::matrix_a, 16, 16, 8, wmma::precision::tf32, wmma::row_major> af[4];
        wmma::fragment<wmma::matrix_b, 16, 16, 8, wmma::precision::tf32, wmma::col_major> bf[4];
        #pragma unroll
        for (int i = 0; i < 4; i++)
            wmma::load_matrix_sync(af[i], abase + i * 16 * 32 + kk * 8, 32);
        #pragma unroll
        for (int j = 0; j < 4; j++)
            wmma::load_matrix_sync(bf[j], bbase + j * 16 * WS_LD + kk * 8, WS_LD);
        #pragma unroll
        for (int i = 0; i < 4; i++)
            #pragma unroll
            for (int j = 0; j < 4; j++)
                wmma::mma_sync(c[i][j], af[i], bf[j], c[i][j]);
    }

    __syncthreads();                   // done reading xs/ws; reuse as cbuf
    float* cb = sm;                    // 256*132 = 33792 floats
    #pragma unroll
    for (int i = 0; i < 4; i++)
        #pragma unroll
        for (int j = 0; j < 4; j++)
            wmma::store_matrix_sync(cb + (wm * 64 + i * 16) * CB_LD + wn * 64 + j * 16,
                                    c[i][j], CB_LD, wmma::mem_row_major);
    __syncthreads();

    for (int idx = tid; idx < 256 * 128; idx += 256) {
        int row = idx >> 7, col = idx & 127;
        int t = t0 + row;
        if (t < STEPS)
            g_hx[((size_t)b * STEPS + t) * DH + J0 + col] =
                cb[row * CB_LD + col] + b1[J0 + col];
    }
}

// ===========================================================================
// Phase B: persistent recurrence. 128 blocks x 256 threads, 2 batch rows each.
// Feedback weights bf16-packed (j, j+256) in smem; W2 in registers; y ring in
// smem read as float4 broadcasts; Hx prefetched w/ __ldcs double-buffer.
// ===========================================================================

__global__ void __launch_bounds__(256, 1)
narx_recur(const float* __restrict__ W1, const float* __restrict__ W2,
           const float* __restrict__ b2, float* __restrict__ out)
{
    extern __shared__ float sm[];
    unsigned* sm_w1 = (unsigned*)sm;       // 32768 u32: [q][jj] pairs (j, j+256)
    float* sm_h  = sm + 32768;             // 1024: h[r][j]
    float* sm_y  = sm_h + 1024;            // 256: y[r][slot][m]
    float* sm_p  = sm_y + 256;             // 512: partials [r][g][m]
    float* sm_b2 = sm_p + 512;             // 32

    const int tid = threadIdx.x;
    const int b0  = blockIdx.x * 2;
    const int m   = tid & 31;
    const int g   = tid >> 5;

    // one-time staging
    for (int idx = tid; idx < 128 * 256; idx += 256) {
        int q = idx >> 8, jj = idx & 255;
        unsigned lo = (unsigned)__bfloat16_as_ushort(
            __float2bfloat16(W1[(size_t)jj * DIN + 256 + q]));
        unsigned hi = (unsigned)__bfloat16_as_ushort(
            __float2bfloat16(W1[(size_t)(jj + 256) * DIN + 256 + q]));
        sm_w1[idx] = lo | (hi << 16);
    }
    sm_y[tid] = 0.0f;                      // 256 entries, one per thread
    if (tid < 32) sm_b2[tid] = b2[tid];
    float w2r[64];
    #pragma unroll
    for (int j = 0; j < 64; j++) w2r[j] = W2[(size_t)m * DH + g * 64 + j];
    __syncthreads();

    const float* hx0 = g_hx + (size_t)b0 * STEPS * DH;
    const float* hx1 = hx0 + (size_t)STEPS * DH;
    float cx0 = __ldcs(hx0 + tid), cx1 = __ldcs(hx0 + tid + 256);
    float cx2 = __ldcs(hx1 + tid), cx3 = __ldcs(hx1 + tid + 256);

    for (int i = 0; i < STEPS; ++i) {
        // prefetch next step's Hx
        float nx0 = 0.f, nx1 = 0.f, nx2 = 0.f, nx3 = 0.f;
        if (i + 1 < STEPS) {
            const float* p0 = hx0 + (size_t)(i + 1) * DH;
            const float* p1 = hx1 + (size_t)(i + 1) * DH;
            nx0 = __ldcs(p0 + tid); nx1 = __ldcs(p0 + tid + 256);
            nx2 = __ldcs(p1 + tid); nx3 = __ldcs(p1 + tid + 256);
        }

        // feedback GEMV: acc[r][j] = Hx + sum_q W1y[j][q] * y[r][q]
        float a00 = cx0, a01 = cx1, a10 = cx2, a11 = cx3;
        #pragma unroll
        for (int d = 0; d < 4; ++d) {
            const int slot = (i + d) & 3;
            const float4* y0 = (const float4*)(sm_y + slot * 32);
            const float4* y1 = (const float4*)(sm_y + 128 + slot * 32);
            const unsigned* wp = sm_w1 + d * 32 * 256 + tid;
            #pragma unroll
            for (int m4 = 0; m4 < 8; ++m4) {
                float4 v0 = y0[m4];
                float4 v1 = y1[m4];
                #pragma unroll
                for (int e = 0; e < 4; ++e) {
                    unsigned p = wp[(m4 * 4 + e) * 256];
                    float wa = __uint_as_float(p << 16);
                    float wb = __uint_as_float(p & 0xffff0000u);
                    float s0 = (e == 0) ? v0.x : (e == 1) ? v0.y : (e == 2) ? v0.z : v0.w;
                    float s1 = (e == 0) ? v1.x : (e == 1) ? v1.y : (e == 2) ? v1.z : v1.w;
                    a00 = fmaf(wa, s0, a00); a01 = fmaf(wb, s0, a01);
                    a10 = fmaf(wa, s1, a10); a11 = fmaf(wb, s1, a11);
                }
            }
        }
        sm_h[tid]       = tanhf(a00);
        sm_h[tid + 256] = tanhf(a01);
        sm_h[512 + tid] = tanhf(a10);
        sm_h[768 + tid] = tanhf(a11);
        __syncthreads();

        // layer 2 partials: thread (m, g) covers j in [g*64, g*64+64)
        float q0 = 0.f, q1 = 0.f;
        const float4* h0 = (const float4*)(sm_h + g * 64);
        const float4* h1 = (const float4*)(sm_h + 512 + g * 64);
        #pragma unroll
        for (int j4 = 0; j4 < 16; ++j4) {
            float4 u0 = h0[j4], u1 = h1[j4];
            q0 = fmaf(w2r[j4 * 4 + 0], u0.x, q0); q1 = fmaf(w2r[j4 * 4 + 0], u1.x, q1);
            q0 = fmaf(w2r[j4 * 4 + 1], u0.y, q0); q1 = fmaf(w2r[j4 * 4 + 1], u1.y, q1);
            q0 = fmaf(w2r[j4 * 4 + 2], u0.z, q0); q1 = fmaf(w2r[j4 * 4 + 2], u1.z, q1);
            q0 = fmaf(w2r[j4 * 4 + 3], u0.w, q0); q1 = fmaf(w2r[j4 * 4 + 3], u1.w, q1);
        }
        sm_p[g * 32 + m]       = q0;
        sm_p[256 + g * 32 + m] = q1;
        __syncthreads();

        // reduce + sigmoid + feedback + output (64 threads)
        if (tid < 64) {
            int r = tid >> 5, mm = tid & 31;
            const float* pp = sm_p + r * 256 + mm;
            float z = pp[0] + pp[32] + pp[64] + pp[96] +
                      pp[128] + pp[160] + pp[192] + pp[224] + sm_b2[mm];
            float o = 1.0f / (1.0f + expf(-z));
            sm_y[r * 128 + (i & 3) * 32 + mm] = o;
            out[((size_t)(b0 + r) * STEPS + i) * DY + mm] = o;
        }
        __syncthreads();

        cx0 = nx0; cx1 = nx1; cx2 = nx2; cx3 = nx3;
    }
}

// ===========================================================================
// launch: inputs (metadata order): x, W1, b1, W2, b2; output fp32 [256,2040,32]
// ===========================================================================

extern "C" void kernel_launch(void* const* d_in, const int* in_sizes, int n_in,
                              void* d_out, int out_size)
{
    const float* x  = (const float*)d_in[0];
    const float* W1 = (const float*)d_in[1];
    const float* b1 = (const float*)d_in[2];
    const float* W2 = (const float*)d_in[3];
    const float* b2 = (const float*)d_in[4];
    float* out = (float*)d_out;
    (void)in_sizes; (void)n_in; (void)out_size;

    constexpr size_t smA = (size_t)(XS_N + 128 * WS_LD) * sizeof(float);            // 168,832 B
    constexpr size_t smB = (size_t)(32768 + 1024 + 256 + 512 + 32) * sizeof(float); // 138,368 B

    cudaFuncSetAttribute(narx_hx, cudaFuncAttributeMaxDynamicSharedMemorySize, (int)smA);
    cudaFuncSetAttribute(narx_recur, cudaFuncAttributeMaxDynamicSharedMemorySize, (int)smB);

    dim3 gA(8, 4, 256);   // t-tiles x j-tiles x batch
    narx_hx<<<gA, 256, smA>>>(x, W1, b1);
    narx_recur<<<128, 256, smB>>>(W1, W2, b2, out);
}

// round 9
// speedup vs baseline: 1.6803x; 1.6803x over previous
#include <cuda_runtime.h>
#include <cuda_fp16.h>
#include <cstdint>

#define BATCH 256
#define TSEQ  2048
#define DH    512
#define STEPS 2040
#define DIN   384

__device__ float g_hx[(size_t)BATCH * STEPS * DH];

__device__ __forceinline__ unsigned su32(const void* p) {
    return (unsigned)__cvta_generic_to_shared(p);
}
__device__ __forceinline__ void ldsm4(unsigned* r, unsigned a) {
    asm volatile("ldmatrix.sync.aligned.m8n8.x4.shared.b16 {%0,%1,%2,%3}, [%4];"
                 : "=r"(r[0]), "=r"(r[1]), "=r"(r[2]), "=r"(r[3]) : "r"(a));
}
__device__ __forceinline__ void ldsm2(unsigned& r0, unsigned& r1, unsigned a) {
    asm volatile("ldmatrix.sync.aligned.m8n8.x2.shared.b16 {%0,%1}, [%2];"
                 : "=r"(r0), "=r"(r1) : "r"(a));
}
__device__ __forceinline__ void mma16816(float* c, const unsigned* a, unsigned b0, unsigned b1) {
    asm volatile("mma.sync.aligned.m16n8k16.row.col.f32.f16.f16.f32 "
                 "{%0,%1,%2,%3}, {%4,%5,%6,%7}, {%8,%9}, {%0,%1,%2,%3};"
                 : "+f"(c[0]), "+f"(c[1]), "+f"(c[2]), "+f"(c[3])
                 : "r"(a[0]), "r"(a[1]), "r"(a[2]), "r"(a[3]), "r"(b0), "r"(b1));
}
__device__ __forceinline__ float tanh_fast(float v) {
    float r; asm("tanh.approx.f32 %0, %1;" : "=f"(r) : "f"(v)); return r;
}

// ===========================================================================
// Phase A: Hx = Xwin[128t x 256k] @ W1x^T, fp16 mma. Tile 128t x 128j.
// x slice padded +8 halves per 32 (row stride 40 halves); W1 stride 264.
// 8 warps = 2(m) x 4(n), warp tile 64x32.
// ===========================================================================
#define WS_LD 264
#define CB_LD 132
#define XSP   5408

__global__ void __launch_bounds__(256, 2)
narx_hx(const float* __restrict__ x, const float* __restrict__ W1,
        const float* __restrict__ b1)
{
    extern __shared__ unsigned char smraw[];
    __half* xs = (__half*)smraw;
    __half* ws = (__half*)(smraw + XSP * 2);
    float*  cb = (float*)(smraw + XSP * 2);     // aliases ws in epilogue

    const int tid = threadIdx.x, warp = tid >> 5, lane = tid & 31;
    const int wm = warp & 1, wn = warp >> 1;
    const int t0 = blockIdx.x * 128, J0 = blockIdx.y * 128, b = blockIdx.z;

    {   // stage x slice (4320 logical), fp16 padded
        const float* xb = x + (size_t)b * (TSEQ * 32) + (size_t)t0 * 32;
        const int lim = TSEQ * 32 - t0 * 32;
        for (int i = tid; i < 4320; i += 256) {
            float v = (i < lim) ? xb[i] : 0.0f;
            xs[(i >> 5) * 40 + (i & 31)] = __float2half_rn(v);
        }
    }
    for (int idx = tid; idx < 128 * 128; idx += 256) {  // W1 x-part [128j][256k]
        int j = idx >> 7, k2 = (idx & 127) << 1;
        const float* w = W1 + (size_t)(J0 + j) * DIN + k2;
        *(__half2*)(ws + j * WS_LD + k2) = __floats2half2_rn(w[0], w[1]);
    }
    __syncthreads();

    float c[4][4][4];
    #pragma unroll
    for (int i = 0; i < 4; i++)
        #pragma unroll
        for (int j = 0; j < 4; j++)
            #pragma unroll
            for (int r = 0; r < 4; r++) c[i][j][r] = 0.0f;

    const unsigned xsb = su32(xs), wsb = su32(ws);
    const int mat = lane >> 3, lrow = lane & 7;

    #pragma unroll 4
    for (int ks = 0; ks < 16; ++ks) {
        unsigned a[4][4], b0[4], b1[4];
        const int col = ks * 16 + (mat >> 1) * 8;
        const int ce  = (col >> 5) * 40 + (col & 31);
        #pragma unroll
        for (int mt = 0; mt < 4; ++mt) {
            int row = wm * 64 + mt * 16 + (mat & 1) * 8 + lrow;
            ldsm4(a[mt], xsb + 2u * (unsigned)(row * 40 + ce));
        }
        const int bcol = ks * 16 + ((lane >> 3) & 1) * 8;
        #pragma unroll
        for (int nt = 0; nt < 4; ++nt) {
            int br = wn * 32 + nt * 8 + lrow;
            ldsm2(b0[nt], b1[nt], wsb + 2u * (unsigned)(br * WS_LD + bcol));
        }
        #pragma unroll
        for (int mt = 0; mt < 4; ++mt)
            #pragma unroll
            for (int nt = 0; nt < 4; ++nt)
                mma16816(c[mt][nt], a[mt], b0[nt], b1[nt]);
    }

    __syncthreads();
    {   // dump accumulators to cb
        const int g = lane >> 2, tq = lane & 3;
        #pragma unroll
        for (int mt = 0; mt < 4; ++mt)
            #pragma unroll
            for (int nt = 0; nt < 4; ++nt) {
                int m0 = wm * 64 + mt * 16 + g, n0 = wn * 32 + nt * 8 + tq * 2;
                *(float2*)(cb + m0 * CB_LD + n0) = make_float2(c[mt][nt][0], c[mt][nt][1]);
                *(float2*)(cb + (m0 + 8) * CB_LD + n0) = make_float2(c[mt][nt][2], c[mt][nt][3]);
            }
    }
    __syncthreads();
    {   // +b1, store fp32 Hx
        const float4 bv = *(const float4*)(b1 + J0 + lane * 4);
        #pragma unroll 4
        for (int rr = 0; rr < 16; ++rr) {
            int row = warp * 16 + rr, t = t0 + row;
            if (t < STEPS) {
                float4 v = *(float4*)(cb + row * CB_LD + lane * 4);
                v.x += bv.x; v.y += bv.y; v.z += bv.z; v.w += bv.w;
                *(float4*)(g_hx + ((size_t)b * STEPS + t) * DH + J0 + lane * 4) = v;
            }
        }
    }
}

// ===========================================================================
// Phase B: 128 blocks x 512 threads (16 warps), 2 batch rows per block.
// Feedback GEMM on tensor pipe: A = Wf[512x128] fp16 frags resident in regs,
// B = y fp16 [8][136] (rows 0,1 real, 2-7 zero), C init = Hx. Layer2 fp32.
// ===========================================================================
#define YLD 136
__global__ void __launch_bounds__(512, 1)
narx_recur(const float* __restrict__ W1, const float* __restrict__ W2,
           const float* __restrict__ b2, float* __restrict__ out)
{
    extern __shared__ unsigned char smraw[];
    __half* wf  = (__half*)smraw;                       // 512*136 halves
    __half* ys  = (__half*)(smraw + 139264);            // 8*136
    float*  sh  = (float*)(smraw + 141440);             // 2*512
    float*  sp  = (float*)(smraw + 145536);             // 2*512
    float*  sb2 = (float*)(smraw + 149632);             // 32
    float*  w2t = (float*)(smraw + 149760);             // [512][32] transposed

    const int tid = threadIdx.x, warp = tid >> 5, lane = tid & 31;
    const int b0 = blockIdx.x * 2;
    const int jb = warp * 32;                           // warp's j base
    const int mat = lane >> 3, lrow = lane & 7;

    // ---- one-time staging ----
    for (int idx = tid; idx < 512 * 64; idx += 512) {   // Wf = W1[:,256:384] fp16
        int j = idx >> 6, q2 = (idx & 63) << 1;
        const float* s = W1 + (size_t)j * DIN + 256 + q2;
        *(__half2*)(wf + j * YLD + q2) = __floats2half2_rn(s[0], s[1]);
    }
    for (int idx = tid; idx < 8 * YLD; idx += 512) ys[idx] = __float2half_rn(0.0f);
    for (int idx = tid; idx < 32 * 512; idx += 512) {   // W2 transposed [j][m]
        int m = idx >> 9, j = idx & 511;
        w2t[j * 32 + m] = W2[(size_t)m * DH + j];
    }
    if (tid < 32) sb2[tid] = b2[tid];
    __syncthreads();

    // preload all Wf A-fragments into registers (2 mt x 8 kt x 4 regs)
    unsigned wfr[2][8][4];
    {
        const unsigned wfb = su32(wf);
        #pragma unroll
        for (int mt = 0; mt < 2; ++mt)
            #pragma unroll
            for (int kt = 0; kt < 8; ++kt) {
                int j = jb + mt * 16 + (mat & 1) * 8 + lrow;
                int q = kt * 16 + (mat >> 1) * 8;
                ldsm4(wfr[mt][kt], wfb + 2u * (unsigned)(j * YLD + q));
            }
    }

    const float* hx0 = g_hx + (size_t)b0 * STEPS * DH;
    const float* hx1 = hx0 + (size_t)STEPS * DH;
    const int m8 = lane >> 2;
    const int ja = jb + m8, jc = jb + 16 + m8;          // frag j coords (+8 sibling)
    const int grp = warp, m = lane;                     // layer2: grp=warp, m=lane

    float cur[8];                                        // Hx for step i
    #pragma unroll
    for (int k = 0; k < 8; ++k) cur[k] = 0.0f;
    cur[0] = __ldcs(hx0 + ja);      cur[1] = __ldcs(hx1 + ja);
    cur[2] = __ldcs(hx0 + ja + 8);  cur[3] = __ldcs(hx1 + ja + 8);
    cur[4] = __ldcs(hx0 + jc);      cur[5] = __ldcs(hx1 + jc);
    cur[6] = __ldcs(hx0 + jc + 8);  cur[7] = __ldcs(hx1 + jc + 8);

    const int yn = lane >> 2, yk = (lane & 3) * 2;      // B-frag coords

    for (int i = 0; i < STEPS; ++i) {
        // C init from Hx (pad-column lanes get same values; results unused)
        float c0[4] = {cur[0], cur[1], cur[2], cur[3]};
        float c1[4] = {cur[4], cur[5], cur[6], cur[7]};

        // prefetch next step Hx
        if (i + 1 < STEPS) {
            const float* p0 = hx0 + (size_t)(i + 1) * DH;
            const float* p1 = hx1 + (size_t)(i + 1) * DH;
            cur[0] = __ldcs(p0 + ja);     cur[1] = __ldcs(p1 + ja);
            cur[2] = __ldcs(p0 + ja + 8); cur[3] = __ldcs(p1 + ja + 8);
            cur[4] = __ldcs(p0 + jc);     cur[5] = __ldcs(p1 + jc);
            cur[6] = __ldcs(p0 + jc + 8); cur[7] = __ldcs(p1 + jc + 8);
        }

        // feedback GEMM: D = Wf @ y^T + Hx
        #pragma unroll
        for (int kt = 0; kt < 8; ++kt) {
            unsigned bb0 = *(const unsigned*)(ys + yn * YLD + kt * 16 + yk);
            unsigned bb1 = *(const unsigned*)(ys + yn * YLD + kt * 16 + 8 + yk);
            mma16816(c0, wfr[0][kt], bb0, bb1);
            mma16816(c1, wfr[1][kt], bb0, bb1);
        }

        // h = tanh, write sh (only lanes holding real columns n=0,1)
        if ((lane & 3) == 0) {
            sh[ja]        = tanh_fast(c0[0]);  sh[512 + ja]      = tanh_fast(c0[1]);
            sh[ja + 8]    = tanh_fast(c0[2]);  sh[512 + ja + 8]  = tanh_fast(c0[3]);
            sh[jc]        = tanh_fast(c1[0]);  sh[512 + jc]      = tanh_fast(c1[1]);
            sh[jc + 8]    = tanh_fast(c1[2]);  sh[512 + jc + 8]  = tanh_fast(c1[3]);
        }
        __syncthreads();                                 // (A) sh ready

        // layer2 partials: thread (warp=grp, lane=m) covers j in [grp*32, +32)
        float q0 = 0.f, q1 = 0.f;
        {
            const float* hj0 = sh + grp * 32;
            const float* hj1 = sh + 512 + grp * 32;
            const float* wj  = w2t + grp * 32 * 32 + m;
            #pragma unroll
            for (int j4 = 0; j4 < 8; ++j4) {
                float4 u0 = *(const float4*)(hj0 + j4 * 4);
                float4 u1 = *(const float4*)(hj1 + j4 * 4);
                float w0 = wj[(j4 * 4 + 0) * 32], w1 = wj[(j4 * 4 + 1) * 32];
                float w2 = wj[(j4 * 4 + 2) * 32], w3 = wj[(j4 * 4 + 3) * 32];
                q0 = fmaf(w0, u0.x, q0); q1 = fmaf(w0, u1.x, q1);
                q0 = fmaf(w1, u0.y, q0); q1 = fmaf(w1, u1.y, q1);
                q0 = fmaf(w2, u0.z, q0); q1 = fmaf(w2, u1.z, q1);
                q0 = fmaf(w3, u0.w, q0); q1 = fmaf(w3, u1.w, q1);
            }
        }
        sp[grp * 32 + m]       = q0;
        sp[512 + grp * 32 + m] = q1;

        // y ring shift read (2 rows x 96)
        __half ysh = __float2half_rn(0.0f);
        int sr = 0, sk = 0;
        if (tid < 192) { sr = tid / 96; sk = tid % 96; ysh = ys[sr * YLD + 32 + sk]; }
        __syncthreads();                                 // (B) sp ready, shift read done

        if (tid < 192) ys[sr * YLD + sk] = ysh;          // shift write
        if (tid < 64) {                                  // reduce + sigmoid + feedback
            int r = tid >> 5, mm = tid & 31;
            const float* pp = sp + r * 512 + mm;
            float z = sb2[mm];
            #pragma unroll
            for (int g = 0; g < 16; ++g) z += pp[g * 32];
            float o = 1.0f / (1.0f + __expf(-z));
            ys[r * YLD + 96 + mm] = __float2half_rn(o);
            out[((size_t)(b0 + r) * STEPS + i) * 32 + mm] = o;
        }
        __syncthreads();                                 // (C) y ready
    }
}

extern "C" void kernel_launch(void* const* d_in, const int* in_sizes, int n_in,
                              void* d_out, int out_size)
{
    const float* x  = (const float*)d_in[0];
    const float* W1 = (const float*)d_in[1];
    const float* b1 = (const float*)d_in[2];
    const float* W2 = (const float*)d_in[3];
    const float* b2 = (const float*)d_in[4];
    float* out = (float*)d_out;
    (void)in_sizes; (void)n_in; (void)out_size;

    constexpr size_t smA = XSP * 2 + 128 * WS_LD * 2;   // 78,400 B
    constexpr size_t smB = 149760 + 512 * 32 * 4;       // 215,296 B

    cudaFuncSetAttribute(narx_hx, cudaFuncAttributeMaxDynamicSharedMemorySize, (int)smA);
    cudaFuncSetAttribute(narx_recur, cudaFuncAttributeMaxDynamicSharedMemorySize, (int)smB);

    dim3 gA(16, 4, 256);
    narx_hx<<<gA, 256, smA>>>(x, W1, b1);
    narx_recur<<<128, 512, smB>>>(W1, W2, b2, out);
}